// round 2
// baseline (speedup 1.0000x reference)
#include <cuda_runtime.h>
#include <cuda_bf16.h>

// Problem constants
#define S_DIM   384
#define N_DIM   512
#define C_DIM   32
#define CZ_DIM  128
#define M_DIM   (S_DIM * C_DIM)     // 12288  (i*32 + c)
#define K2_DIM  (C_DIM * C_DIM)     // 1024   (c*32 + d)

// Scratch: a/b projected activations, stored K-major-transposed:
// g_AT[n][i*32 + c], g_BT[n][j*32 + d]
__device__ float g_AT[N_DIM * M_DIM];
__device__ float g_BT[N_DIM * M_DIM];

// ---------------------------------------------------------------------------
// Kernel 1: LayerNorm over C=32 + projection to a (scaled by 1/512) and b.
// One warp per (s, n) row. 8 warps per block.
// ---------------------------------------------------------------------------
__global__ __launch_bounds__(256) void ln_proj_kernel(
    const float* __restrict__ m_si,
    const float* __restrict__ ln_g,
    const float* __restrict__ ln_b,
    const float* __restrict__ w_ab)
{
    __shared__ float ws[64 * 33];   // padded to kill 32-way bank conflicts

    int t = threadIdx.x;
    for (int idx = t; idx < 64 * 32; idx += 256) {
        int d = idx >> 5, c = idx & 31;
        ws[d * 33 + c] = w_ab[idx];
    }
    __syncthreads();

    int warp = t >> 5, lane = t & 31;
    int r = blockIdx.x * 8 + warp;          // row in [0, 384*512)
    int s = r >> 9;                         // N_DIM = 512
    int n = r & 511;

    float x = m_si[r * 32 + lane];

    // mean
    float sum = x;
    #pragma unroll
    for (int o = 16; o; o >>= 1) sum += __shfl_xor_sync(0xFFFFFFFFu, sum, o);
    float mu = sum * (1.0f / 32.0f);
    float dx = x - mu;

    // variance
    float v = dx * dx;
    #pragma unroll
    for (int o = 16; o; o >>= 1) v += __shfl_xor_sync(0xFFFFFFFFu, v, o);
    float rstd = rsqrtf(v * (1.0f / 32.0f) + 1e-5f);

    float mn = dx * rstd * ln_g[lane] + ln_b[lane];

    // ab[d] = sum_c mn[c] * w_ab[d][c]; lane computes d=lane (a) and d=lane+32 (b)
    float acc_a = 0.0f, acc_b = 0.0f;
    #pragma unroll
    for (int c = 0; c < 32; c++) {
        float mc = __shfl_sync(0xFFFFFFFFu, mn, c);
        acc_a += mc * ws[lane * 33 + c];
        acc_b += mc * ws[(lane + 32) * 33 + c];
    }

    // coalesced stores (lane-contiguous in m)
    g_AT[n * M_DIM + s * 32 + lane] = acc_a * (1.0f / 512.0f);  // fold 1/n_seq
    g_BT[n * M_DIM + s * 32 + lane] = acc_b;
}

// ---------------------------------------------------------------------------
// Kernel 2: fused o-tile GEMM + w_final contraction.
// Each CTA: 128x128 tile of o = AT^T * BT (K = 512), i.e. 4 i-values x 4
// j-values = 16 (i,j) pairs. Then z[pair][0..127] = W * o_vec[pair] + bias.
// 256 threads, 8x8 register blocking (strided, conflict-free scalar LDS).
// ---------------------------------------------------------------------------
#define BM 128
#define BN 128
#define KT 8
#define OSM_STRIDE (K2_DIM + 8)     // 1032 floats; 4128 B rows, 16B aligned

extern __shared__ float smem_buf[];

__global__ __launch_bounds__(256, 2) void opm_fused_kernel(
    const float* __restrict__ w_final,
    const float* __restrict__ b_final,
    float* __restrict__ z)
{
    float* As = smem_buf;                 // [KT][BM]
    float* Bs = smem_buf + KT * BM;       // [KT][BN]
    float* osm = smem_buf;                // reused: [16][OSM_STRIDE]

    int t  = threadIdx.x;
    int tm = t >> 4;                      // 0..15
    int tn = t & 15;                      // 0..15
    int m0 = blockIdx.y * BM;
    int p0 = blockIdx.x * BN;

    float acc[8][8];
    #pragma unroll
    for (int u = 0; u < 8; u++)
        #pragma unroll
        for (int v = 0; v < 8; v++) acc[u][v] = 0.0f;

    for (int k0 = 0; k0 < N_DIM; k0 += KT) {
        // cooperative tile load: 8x128 each, coalesced along m
        #pragma unroll
        for (int q = 0; q < 4; q++) {
            int idx = t + q * 256;                  // 0..1023
            int kk = idx >> 7, mm = idx & 127;
            As[kk * BM + mm] = g_AT[(k0 + kk) * M_DIM + m0 + mm];
            Bs[kk * BN + mm] = g_BT[(k0 + kk) * M_DIM + p0 + mm];
        }
        __syncthreads();

        #pragma unroll
        for (int kk = 0; kk < KT; kk++) {
            float ra[8], rb[8];
            #pragma unroll
            for (int u = 0; u < 8; u++) ra[u] = As[kk * BM + tm + u * 16];
            #pragma unroll
            for (int v = 0; v < 8; v++) rb[v] = Bs[kk * BN + tn + v * 16];
            #pragma unroll
            for (int u = 0; u < 8; u++)
                #pragma unroll
                for (int v = 0; v < 8; v++)
                    acc[u][v] += ra[u] * rb[v];
        }
        __syncthreads();
    }

    // Park o tile in SMEM, transposed into pair-major [pair][k=c*32+d] layout.
    // Thread's acc[u][v] is o at (row_local = tm + 16u, col_local = tn + 16v).
    #pragma unroll
    for (int u = 0; u < 8; u++) {
        int rl = tm + u * 16;
        #pragma unroll
        for (int v = 0; v < 8; v++) {
            int cl = tn + v * 16;
            int pair = ((rl >> 5) << 2) | (cl >> 5);
            int k    = ((rl & 31) << 5) | (cl & 31);
            osm[pair * OSM_STRIDE + k] = acc[u][v];
        }
    }
    __syncthreads();

    // Epilogue GEMM: z[pair][zz] = sum_k osm[pair][k] * w_final[zz][k] + bias
    // Each thread: 2 pairs x 4 zz outputs, K = 1024, unrolled by 4 (float4).
    int pb  = (t & 7) * 2;        // pair base: 0,2,...,14
    int zz0 = (t >> 3) * 4;       // 0,4,...,124

    float zacc[2][4];
    #pragma unroll
    for (int p = 0; p < 2; p++)
        #pragma unroll
        for (int q = 0; q < 4; q++) zacc[p][q] = 0.0f;

    const float4* Wv = reinterpret_cast<const float4*>(w_final);
    const float4* o0p = reinterpret_cast<const float4*>(&osm[pb * OSM_STRIDE]);
    const float4* o1p = reinterpret_cast<const float4*>(&osm[(pb + 1) * OSM_STRIDE]);

    #pragma unroll 4
    for (int k4 = 0; k4 < K2_DIM / 4; k4++) {
        float4 o0 = o0p[k4];
        float4 o1 = o1p[k4];
        #pragma unroll
        for (int q = 0; q < 4; q++) {
            float4 w = Wv[(zz0 + q) * (K2_DIM / 4) + k4];
            zacc[0][q] += o0.x * w.x + o0.y * w.y + o0.z * w.z + o0.w * w.w;
            zacc[1][q] += o1.x * w.x + o1.y * w.y + o1.z * w.z + o1.w * w.w;
        }
    }

    int i0 = blockIdx.y * 4;     // 4 i-values per tile (BM/32)
    int j0 = blockIdx.x * 4;
    #pragma unroll
    for (int p = 0; p < 2; p++) {
        int pr = pb + p;
        int i = i0 + (pr >> 2);
        int j = j0 + (pr & 3);
        #pragma unroll
        for (int q = 0; q < 4; q++) {
            z[(i * S_DIM + j) * CZ_DIM + zz0 + q] = zacc[p][q] + b_final[zz0 + q];
        }
    }
}

// ---------------------------------------------------------------------------
extern "C" void kernel_launch(void* const* d_in, const int* in_sizes, int n_in,
                              void* d_out, int out_size)
{
    const float* m_si    = (const float*)d_in[0];
    const float* ln_g    = (const float*)d_in[1];
    const float* ln_b    = (const float*)d_in[2];
    const float* w_ab    = (const float*)d_in[3];
    const float* w_final = (const float*)d_in[4];
    const float* b_final = (const float*)d_in[5];
    float* z = (float*)d_out;

    (void)in_sizes; (void)n_in; (void)out_size;

    ln_proj_kernel<<<(S_DIM * N_DIM) / 8, 256>>>(m_si, ln_g, ln_b, w_ab);

    const int smem_bytes = 16 * OSM_STRIDE * sizeof(float);   // 66048 B
    cudaFuncSetAttribute(opm_fused_kernel,
                         cudaFuncAttributeMaxDynamicSharedMemorySize, smem_bytes);
    dim3 grid(S_DIM / 4, S_DIM / 4);   // 96 x 96 CTAs
    opm_fused_kernel<<<grid, 256, smem_bytes>>>(w_final, b_final, z);
}

// round 3
// speedup vs baseline: 1.6428x; 1.6428x over previous
#include <cuda_runtime.h>
#include <cuda_bf16.h>

// Problem constants
#define S_DIM   384
#define N_DIM   512
#define C_DIM   32
#define CZ_DIM  128
#define M_DIM   (S_DIM * C_DIM)     // 12288  (i*32 + c)
#define K2_DIM  (C_DIM * C_DIM)     // 1024   (c*32 + d)

// Scratch: a/b projected activations, stored K-major-transposed:
// g_AT[n][i*32 + c], g_BT[n][j*32 + d]
__device__ float g_AT[N_DIM * M_DIM];
__device__ float g_BT[N_DIM * M_DIM];

// ---------------------------------------------------------------------------
// Kernel 1: LayerNorm over C=32 + projection to a (scaled by 1/512) and b.
// One warp per (s, n) row. 8 warps per block.
// ---------------------------------------------------------------------------
__global__ __launch_bounds__(256) void ln_proj_kernel(
    const float* __restrict__ m_si,
    const float* __restrict__ ln_g,
    const float* __restrict__ ln_b,
    const float* __restrict__ w_ab)
{
    __shared__ float ws[64 * 33];   // padded to kill 32-way bank conflicts

    int t = threadIdx.x;
    for (int idx = t; idx < 64 * 32; idx += 256) {
        int d = idx >> 5, c = idx & 31;
        ws[d * 33 + c] = w_ab[idx];
    }
    __syncthreads();

    int warp = t >> 5, lane = t & 31;
    int r = blockIdx.x * 8 + warp;          // row in [0, 384*512)
    int s = r >> 9;                         // N_DIM = 512
    int n = r & 511;

    float x = m_si[r * 32 + lane];

    // mean
    float sum = x;
    #pragma unroll
    for (int o = 16; o; o >>= 1) sum += __shfl_xor_sync(0xFFFFFFFFu, sum, o);
    float mu = sum * (1.0f / 32.0f);
    float dx = x - mu;

    // variance
    float v = dx * dx;
    #pragma unroll
    for (int o = 16; o; o >>= 1) v += __shfl_xor_sync(0xFFFFFFFFu, v, o);
    float rstd = rsqrtf(v * (1.0f / 32.0f) + 1e-5f);

    float mn = dx * rstd * ln_g[lane] + ln_b[lane];

    // ab[d] = sum_c mn[c] * w_ab[d][c]; lane computes d=lane (a) and d=lane+32 (b)
    float acc_a = 0.0f, acc_b = 0.0f;
    #pragma unroll
    for (int c = 0; c < 32; c++) {
        float mc = __shfl_sync(0xFFFFFFFFu, mn, c);
        acc_a += mc * ws[lane * 33 + c];
        acc_b += mc * ws[(lane + 32) * 33 + c];
    }

    // coalesced stores (lane-contiguous in m)
    g_AT[n * M_DIM + s * 32 + lane] = acc_a * (1.0f / 512.0f);  // fold 1/n_seq
    g_BT[n * M_DIM + s * 32 + lane] = acc_b;
}

// ---------------------------------------------------------------------------
// Kernel 2: fused o-tile GEMM + w_final contraction.
// Each CTA: 128x128 tile of o = AT^T * BT (K = 512), i.e. 4 i-values x 4
// j-values = 16 (i,j) pairs. Then z[pair][0..127] = W * o_vec[pair] + bias.
// 256 threads, 8x8 register blocking (strided, conflict-free scalar LDS).
// ---------------------------------------------------------------------------
#define BM 128
#define BN 128
#define KT 8
#define OSM_STRIDE (K2_DIM + 8)     // 1032 floats; 4128 B rows, 16B aligned

extern __shared__ float smem_buf[];

__global__ __launch_bounds__(256, 2) void opm_fused_kernel(
    const float* __restrict__ w_final,
    const float* __restrict__ b_final,
    float* __restrict__ z)
{
    float* As = smem_buf;                 // [KT][BM]
    float* Bs = smem_buf + KT * BM;       // [KT][BN]
    float* osm = smem_buf;                // reused: [16][OSM_STRIDE]

    int t  = threadIdx.x;
    int tm = t >> 4;                      // 0..15
    int tn = t & 15;                      // 0..15
    int m0 = blockIdx.y * BM;
    int p0 = blockIdx.x * BN;

    float acc[8][8];
    #pragma unroll
    for (int u = 0; u < 8; u++)
        #pragma unroll
        for (int v = 0; v < 8; v++) acc[u][v] = 0.0f;

    for (int k0 = 0; k0 < N_DIM; k0 += KT) {
        // cooperative tile load: 8x128 each, coalesced along m
        #pragma unroll
        for (int q = 0; q < 4; q++) {
            int idx = t + q * 256;                  // 0..1023
            int kk = idx >> 7, mm = idx & 127;
            As[kk * BM + mm] = g_AT[(k0 + kk) * M_DIM + m0 + mm];
            Bs[kk * BN + mm] = g_BT[(k0 + kk) * M_DIM + p0 + mm];
        }
        __syncthreads();

        #pragma unroll
        for (int kk = 0; kk < KT; kk++) {
            float ra[8], rb[8];
            #pragma unroll
            for (int u = 0; u < 8; u++) ra[u] = As[kk * BM + tm + u * 16];
            #pragma unroll
            for (int v = 0; v < 8; v++) rb[v] = Bs[kk * BN + tn + v * 16];
            #pragma unroll
            for (int u = 0; u < 8; u++)
                #pragma unroll
                for (int v = 0; v < 8; v++)
                    acc[u][v] += ra[u] * rb[v];
        }
        __syncthreads();
    }

    // Park o tile in SMEM, transposed into pair-major [pair][k=c*32+d] layout.
    // Thread's acc[u][v] is o at (row_local = tm + 16u, col_local = tn + 16v).
    #pragma unroll
    for (int u = 0; u < 8; u++) {
        int rl = tm + u * 16;
        #pragma unroll
        for (int v = 0; v < 8; v++) {
            int cl = tn + v * 16;
            int pair = ((rl >> 5) << 2) | (cl >> 5);
            int k    = ((rl & 31) << 5) | (cl & 31);
            osm[pair * OSM_STRIDE + k] = acc[u][v];
        }
    }
    __syncthreads();

    // Epilogue GEMM: z[pair][zz] = sum_k osm[pair][k] * w_final[zz][k] + bias
    // Each thread: 2 pairs x 4 zz outputs, K = 1024, unrolled by 4 (float4).
    int pb  = (t & 7) * 2;        // pair base: 0,2,...,14
    int zz0 = (t >> 3) * 4;       // 0,4,...,124

    float zacc[2][4];
    #pragma unroll
    for (int p = 0; p < 2; p++)
        #pragma unroll
        for (int q = 0; q < 4; q++) zacc[p][q] = 0.0f;

    const float4* Wv = reinterpret_cast<const float4*>(w_final);
    const float4* o0p = reinterpret_cast<const float4*>(&osm[pb * OSM_STRIDE]);
    const float4* o1p = reinterpret_cast<const float4*>(&osm[(pb + 1) * OSM_STRIDE]);

    #pragma unroll 4
    for (int k4 = 0; k4 < K2_DIM / 4; k4++) {
        float4 o0 = o0p[k4];
        float4 o1 = o1p[k4];
        #pragma unroll
        for (int q = 0; q < 4; q++) {
            float4 w = Wv[(zz0 + q) * (K2_DIM / 4) + k4];
            zacc[0][q] += o0.x * w.x + o0.y * w.y + o0.z * w.z + o0.w * w.w;
            zacc[1][q] += o1.x * w.x + o1.y * w.y + o1.z * w.z + o1.w * w.w;
        }
    }

    int i0 = blockIdx.y * 4;     // 4 i-values per tile (BM/32)
    int j0 = blockIdx.x * 4;
    #pragma unroll
    for (int p = 0; p < 2; p++) {
        int pr = pb + p;
        int i = i0 + (pr >> 2);
        int j = j0 + (pr & 3);
        #pragma unroll
        for (int q = 0; q < 4; q++) {
            z[(i * S_DIM + j) * CZ_DIM + zz0 + q] = zacc[p][q] + b_final[zz0 + q];
        }
    }
}

// ---------------------------------------------------------------------------
extern "C" void kernel_launch(void* const* d_in, const int* in_sizes, int n_in,
                              void* d_out, int out_size)
{
    const float* m_si    = (const float*)d_in[0];
    const float* ln_g    = (const float*)d_in[1];
    const float* ln_b    = (const float*)d_in[2];
    const float* w_ab    = (const float*)d_in[3];
    const float* w_final = (const float*)d_in[4];
    const float* b_final = (const float*)d_in[5];
    float* z = (float*)d_out;

    (void)in_sizes; (void)n_in; (void)out_size;

    ln_proj_kernel<<<(S_DIM * N_DIM) / 8, 256>>>(m_si, ln_g, ln_b, w_ab);

    const int smem_bytes = 16 * OSM_STRIDE * sizeof(float);   // 66048 B
    cudaFuncSetAttribute(opm_fused_kernel,
                         cudaFuncAttributeMaxDynamicSharedMemorySize, smem_bytes);
    dim3 grid(S_DIM / 4, S_DIM / 4);   // 96 x 96 CTAs
    opm_fused_kernel<<<grid, 256, smem_bytes>>>(w_final, b_final, z);
}